// round 2
// baseline (speedup 1.0000x reference)
#include <cuda_runtime.h>
#include <cstdint>

#define NQ   512
#define SS   2048
#define DD   128
#define TOPK 32
#define CLS  1000

__device__ float g_summary[NQ * DD];

__device__ __forceinline__ float warp_sum(float v) {
    #pragma unroll
    for (int o = 16; o > 0; o >>= 1) v += __shfl_xor_sync(0xffffffffu, v, o);
    return v;
}

__global__ __launch_bounds__(256, 4) void attn_topk_kernel(
    const float* __restrict__ q,
    const float* __restrict__ Kmat,
    const float* __restrict__ Vmat,
    float* __restrict__ weights_out)
{
    const int n    = blockIdx.x;
    const int tid  = threadIdx.x;
    const int warp = tid >> 5;
    const int lane = tid & 31;

    __shared__ float logits[SS];
    __shared__ float cand_v[256];
    __shared__ int   cand_i[256];
    __shared__ float s_topv[TOPK];
    __shared__ int   s_topi[TOPK];
    __shared__ float s_w[TOPK];

    const float NEG_INF = __int_as_float(0xff800000);
    const float scale   = 0.08838834764831845f; // 1/sqrt(128)

    const float4 qv = reinterpret_cast<const float4*>(q + (size_t)n * DD)[lane];
    const float4* __restrict__ K4 =
        reinterpret_cast<const float4*>(Kmat + (size_t)n * SS * DD);

    // ---- Phase A: logits. warp-per-row, 8 rows in flight (high MLP) ----
    for (int s0 = warp * 8; s0 < SS; s0 += 64) {
        float4 kk[8];
        #pragma unroll
        for (int r = 0; r < 8; r++)
            kk[r] = __ldcs(&K4[(size_t)(s0 + r) * 32 + lane]);
        float p[8];
        #pragma unroll
        for (int r = 0; r < 8; r++)
            p[r] = qv.x*kk[r].x + qv.y*kk[r].y + qv.z*kk[r].z + qv.w*kk[r].w;
        #pragma unroll
        for (int r = 0; r < 8; r++)
            p[r] = warp_sum(p[r]);
        if (lane == 0) {
            #pragma unroll
            for (int r = 0; r < 8; r++)
                logits[s0 + r] = p[r] * scale;
        }
    }

    // zero the weights output row (overlaps with other CTAs' streaming)
    {
        float4 z = make_float4(0.f, 0.f, 0.f, 0.f);
        float4* w4 = reinterpret_cast<float4*>(weights_out + (size_t)n * SS);
        #pragma unroll
        for (int i = tid; i < SS / 4; i += 256) w4[i] = z;
    }
    __syncthreads();

    // ---- Phase B1: per-warp top-32 of its 256 logits (barrier-free) ----
    {
        float r[8];
        const int base = warp * 256 + lane;
        #pragma unroll
        for (int j = 0; j < 8; j++) r[j] = logits[base + j * 32];

        #pragma unroll 1
        for (int k = 0; k < TOPK; k++) {
            float bv = r[0]; int bj = 0;
            #pragma unroll
            for (int j = 1; j < 8; j++)
                if (r[j] > bv) { bv = r[j]; bj = j; }
            int bi = warp * 256 + bj * 32 + lane;
            #pragma unroll
            for (int o = 16; o > 0; o >>= 1) {
                float ov = __shfl_xor_sync(0xffffffffu, bv, o);
                int   oi = __shfl_xor_sync(0xffffffffu, bi, o);
                if (ov > bv || (ov == bv && oi < bi)) { bv = ov; bi = oi; }
            }
            // owner lane removes the winner from its registers
            if (lane == (bi & 31)) {
                int jw = (bi >> 5) & 7;
                #pragma unroll
                for (int j = 0; j < 8; j++)
                    if (j == jw) r[j] = NEG_INF;
            }
            if (lane == 0) { cand_v[warp * 32 + k] = bv; cand_i[warp * 32 + k] = bi; }
        }
    }
    __syncthreads();

    // ---- Phase B2: warp 0 merges 256 candidates -> global top-32; softmax ----
    if (warp == 0) {
        float cv[8];
        #pragma unroll
        for (int j = 0; j < 8; j++) cv[j] = cand_v[j * 32 + lane];

        #pragma unroll 1
        for (int k = 0; k < TOPK; k++) {
            float bv = cv[0]; int bj = 0;
            #pragma unroll
            for (int j = 1; j < 8; j++)
                if (cv[j] > bv) { bv = cv[j]; bj = j; }
            int bp = bj * 32 + lane;   // position; pos-order == idx-order on ties
            #pragma unroll
            for (int o = 16; o > 0; o >>= 1) {
                float ov = __shfl_xor_sync(0xffffffffu, bv, o);
                int   op = __shfl_xor_sync(0xffffffffu, bp, o);
                if (ov > bv || (ov == bv && op < bp)) { bv = ov; bp = op; }
            }
            if (lane == (bp & 31)) {
                int jw = bp >> 5;
                #pragma unroll
                for (int j = 0; j < 8; j++)
                    if (j == jw) cv[j] = NEG_INF;
            }
            if (lane == 0) { s_topv[k] = bv; s_topi[k] = cand_i[bp]; }
        }
        __syncwarp();

        // softmax over 32 kept values
        float v = s_topv[lane];
        float m = s_topv[0];          // first extraction = global max
        float e = expf(v - m);
        float denom = warp_sum(e);
        s_w[lane] = e / denom;
    }
    __syncthreads();

    // ---- Phase D: summary[n, d] = sum_k w[k] * V[n, idx[k], d] ----
    if (tid < DD) {
        float acc = 0.f;
        #pragma unroll
        for (int i = 0; i < TOPK; i++)
            acc += s_w[i] * Vmat[((size_t)n * SS + s_topi[i]) * DD + tid];
        g_summary[n * DD + tid] = acc;
    }

    // ---- Phase E: scatter weights ----
    if (tid < TOPK) {
        weights_out[(size_t)n * SS + s_topi[tid]] = s_w[tid];
    }
}

// Fused readout: out[n,c] = sum_d summary[n,d]*W[c,d] + bias[c]
// blockIdx.x < 16 -> cls (C=1000); else -> rec (C=128).
__global__ __launch_bounds__(256) void readout_gemm(
    const float* __restrict__ Wc, const float* __restrict__ bc, float* __restrict__ outc,
    const float* __restrict__ Wr, const float* __restrict__ br, float* __restrict__ outr)
{
    const float* W;  const float* bias;  float* out;  int C;  int cTile;
    if (blockIdx.x < 16) { W = Wc; bias = bc; out = outc; C = CLS; cTile = blockIdx.x * 64; }
    else                 { W = Wr; bias = br; out = outr; C = DD;  cTile = (blockIdx.x - 16) * 64; }

    const int tx = threadIdx.x & 15;
    const int ty = threadIdx.x >> 4;
    const int nTile = blockIdx.y * 64;

    __shared__ float As[32][65];
    __shared__ float Bs[32][65];

    float acc[4][4];
    #pragma unroll
    for (int i = 0; i < 4; i++)
        #pragma unroll
        for (int j = 0; j < 4; j++) acc[i][j] = 0.f;

    for (int k0 = 0; k0 < DD; k0 += 32) {
        #pragma unroll
        for (int e = 0; e < 8; e++) {
            int linear = threadIdx.x + e * 256;
            int rr = linear >> 5;
            int kk = linear & 31;
            As[kk][rr] = g_summary[(nTile + rr) * DD + k0 + kk];
            int cg = cTile + rr;
            Bs[kk][rr] = (cg < C) ? W[(size_t)cg * DD + k0 + kk] : 0.f;
        }
        __syncthreads();
        #pragma unroll
        for (int kk = 0; kk < 32; kk++) {
            float a[4], b[4];
            #pragma unroll
            for (int i = 0; i < 4; i++) a[i] = As[kk][ty * 4 + i];
            #pragma unroll
            for (int j = 0; j < 4; j++) b[j] = Bs[kk][tx * 4 + j];
            #pragma unroll
            for (int i = 0; i < 4; i++)
                #pragma unroll
                for (int j = 0; j < 4; j++)
                    acc[i][j] += a[i] * b[j];
        }
        __syncthreads();
    }

    #pragma unroll
    for (int i = 0; i < 4; i++) {
        int nn = nTile + ty * 4 + i;
        #pragma unroll
        for (int j = 0; j < 4; j++) {
            int cg = cTile + tx * 4 + j;
            if (cg < C) out[(size_t)nn * C + cg] = acc[i][j] + bias[cg];
        }
    }
}

extern "C" void kernel_launch(void* const* d_in, const int* in_sizes, int n_in,
                              void* d_out, int out_size) {
    const float* q     = (const float*)d_in[0];
    const float* Kmat  = (const float*)d_in[1];
    const float* Vmat  = (const float*)d_in[2];
    const float* W_cls = (const float*)d_in[3];
    const float* b_cls = (const float*)d_in[4];
    const float* W_rec = (const float*)d_in[5];
    const float* b_rec = (const float*)d_in[6];

    float* out = (float*)d_out;
    float* cls = out;
    float* rec = out + (size_t)NQ * CLS;
    float* wts = rec + (size_t)NQ * DD;

    attn_topk_kernel<<<NQ, 256>>>(q, Kmat, Vmat, wts);
    readout_gemm<<<dim3(18, NQ / 64), 256>>>(W_cls, b_cls, cls, W_rec, b_rec, rec);
}

// round 3
// speedup vs baseline: 1.1884x; 1.1884x over previous
#include <cuda_runtime.h>
#include <cstdint>

#define NQ   512
#define SS   2048
#define DD   128
#define TOPK 32
#define CLS  1000

#define TS   32                 // K rows per stage
#define NT   (SS / TS)          // 64 tiles

__device__ float g_summary[NQ * DD];

__device__ __forceinline__ float warp_sum(float v) {
    #pragma unroll
    for (int o = 16; o > 0; o >>= 1) v += __shfl_xor_sync(0xffffffffu, v, o);
    return v;
}

__device__ __forceinline__ void cp_async16(void* smem, const void* gmem) {
    uint32_t s = (uint32_t)__cvta_generic_to_shared(smem);
    asm volatile("cp.async.cg.shared.global [%0], [%1], 16;" :: "r"(s), "l"(gmem));
}

__global__ __launch_bounds__(256, 4) void attn_topk_kernel(
    const float* __restrict__ q,
    const float* __restrict__ Kmat,
    const float* __restrict__ Vmat,
    float* __restrict__ weights_out)
{
    const int n    = blockIdx.x;
    const int tid  = threadIdx.x;
    const int warp = tid >> 5;
    const int lane = tid & 31;

    __shared__ float kbuf[2][TS * DD];   // 32 KB double buffer
    __shared__ float logits[SS];         // 8 KB
    __shared__ float cand_v[256];
    __shared__ int   cand_i[256];
    __shared__ float s_topv[TOPK];
    __shared__ int   s_topi[TOPK];
    __shared__ float s_w[TOPK];

    const float NEG_INF = __int_as_float(0xff800000);
    const float scale   = 0.08838834764831845f; // 1/sqrt(128)

    // thread -> (row within tile, group): 8 threads per row
    const int row = tid >> 3;      // 0..31
    const int g   = tid & 7;       // 0..7

    // q fragment for this thread: floats {g*4 + j*32 .. +3}, j = 0..3
    float4 qf[4];
    {
        const float* qrow = q + (size_t)n * DD;
        #pragma unroll
        for (int j = 0; j < 4; j++)
            qf[j] = *reinterpret_cast<const float4*>(qrow + g * 4 + j * 32);
    }

    const float* __restrict__ Ksrc = Kmat + (size_t)n * SS * DD;

    // zero the weights output row up front (independent DRAM writes)
    {
        float4 z = make_float4(0.f, 0.f, 0.f, 0.f);
        float4* w4 = reinterpret_cast<float4*>(weights_out + (size_t)n * SS);
        #pragma unroll
        for (int i = tid; i < SS / 4; i += 256) w4[i] = z;
    }

    // ---- Phase A: logits via cp.async double-buffered pipeline ----
    // prefetch tile 0
    #pragma unroll
    for (int i = 0; i < 4; i++) {
        int c = tid + i * 256;                    // 16B chunk id, 0..1023
        cp_async16(&kbuf[0][c * 4], Ksrc + c * 4);
    }
    asm volatile("cp.async.commit_group;");

    for (int t = 0; t < NT; t++) {
        if (t + 1 < NT) {
            const float* src = Ksrc + (size_t)(t + 1) * TS * DD;
            float* dst = kbuf[(t + 1) & 1];
            #pragma unroll
            for (int i = 0; i < 4; i++) {
                int c = tid + i * 256;
                cp_async16(&dst[c * 4], src + c * 4);
            }
            asm volatile("cp.async.commit_group;");
            asm volatile("cp.async.wait_group 1;");
        } else {
            asm volatile("cp.async.wait_group 0;");
        }
        __syncthreads();

        // compute: this thread's partial dot for row `row` of tile t
        const float* kb = &kbuf[t & 1][row * DD];
        float p = 0.f;
        #pragma unroll
        for (int j = 0; j < 4; j++) {
            float4 kv = *reinterpret_cast<const float4*>(kb + g * 4 + j * 32);
            p += qf[j].x * kv.x + qf[j].y * kv.y + qf[j].z * kv.z + qf[j].w * kv.w;
        }
        // reduce across the 8-thread group
        p += __shfl_xor_sync(0xffffffffu, p, 1);
        p += __shfl_xor_sync(0xffffffffu, p, 2);
        p += __shfl_xor_sync(0xffffffffu, p, 4);
        if (g == 0) logits[t * TS + row] = p * scale;
        __syncthreads();
    }

    // ---- Phase B1: per-warp top-32 of its 256 logits (barrier-free) ----
    {
        float r[8];
        const int base = warp * 256 + lane;
        #pragma unroll
        for (int j = 0; j < 8; j++) r[j] = logits[base + j * 32];

        #pragma unroll 1
        for (int k = 0; k < TOPK; k++) {
            float bv = r[0]; int bj = 0;
            #pragma unroll
            for (int j = 1; j < 8; j++)
                if (r[j] > bv) { bv = r[j]; bj = j; }
            int bi = warp * 256 + bj * 32 + lane;
            #pragma unroll
            for (int o = 16; o > 0; o >>= 1) {
                float ov = __shfl_xor_sync(0xffffffffu, bv, o);
                int   oi = __shfl_xor_sync(0xffffffffu, bi, o);
                if (ov > bv || (ov == bv && oi < bi)) { bv = ov; bi = oi; }
            }
            if (lane == (bi & 31)) {
                int jw = (bi >> 5) & 7;
                #pragma unroll
                for (int j = 0; j < 8; j++)
                    if (j == jw) r[j] = NEG_INF;
            }
            if (lane == 0) { cand_v[warp * 32 + k] = bv; cand_i[warp * 32 + k] = bi; }
        }
    }
    __syncthreads();

    // ---- Phase B2: warp 0 merges 256 candidates -> top-32; softmax ----
    if (warp == 0) {
        float cv[8];
        #pragma unroll
        for (int j = 0; j < 8; j++) cv[j] = cand_v[j * 32 + lane];

        #pragma unroll 1
        for (int k = 0; k < TOPK; k++) {
            float bv = cv[0]; int bj = 0;
            #pragma unroll
            for (int j = 1; j < 8; j++)
                if (cv[j] > bv) { bv = cv[j]; bj = j; }
            int bp = bj * 32 + lane;   // position order == index order on ties
            #pragma unroll
            for (int o = 16; o > 0; o >>= 1) {
                float ov = __shfl_xor_sync(0xffffffffu, bv, o);
                int   op = __shfl_xor_sync(0xffffffffu, bp, o);
                if (ov > bv || (ov == bv && op < bp)) { bv = ov; bp = op; }
            }
            if (lane == (bp & 31)) {
                int jw = bp >> 5;
                #pragma unroll
                for (int j = 0; j < 8; j++)
                    if (j == jw) cv[j] = NEG_INF;
            }
            if (lane == 0) { s_topv[k] = bv; s_topi[k] = cand_i[bp]; }
        }
        __syncwarp();

        float v = s_topv[lane];
        float m = s_topv[0];           // first extraction == global max
        float e = expf(v - m);
        float denom = warp_sum(e);
        s_w[lane] = e / denom;
    }
    __syncthreads();

    // ---- Phase D: summary[n, d] = sum_k w[k] * V[n, idx[k], d] ----
    if (tid < DD) {
        float acc = 0.f;
        #pragma unroll
        for (int i = 0; i < TOPK; i++)
            acc += s_w[i] * Vmat[((size_t)n * SS + s_topi[i]) * DD + tid];
        g_summary[n * DD + tid] = acc;
    }

    // ---- Phase E: scatter weights ----
    if (tid < TOPK) {
        weights_out[(size_t)n * SS + s_topi[tid]] = s_w[tid];
    }
}

// Fused readout: out[n,c] = sum_d summary[n,d]*W[c,d] + bias[c]
// Tiles: C=64, N=32. blockIdx.x < 16 -> cls (C=1000); else -> rec (C=128).
__global__ __launch_bounds__(256) void readout_gemm(
    const float* __restrict__ Wc, const float* __restrict__ bc, float* __restrict__ outc,
    const float* __restrict__ Wr, const float* __restrict__ br, float* __restrict__ outr)
{
    const float* W;  const float* bias;  float* out;  int C;  int cTile;
    if (blockIdx.x < 16) { W = Wc; bias = bc; out = outc; C = CLS; cTile = blockIdx.x * 64; }
    else                 { W = Wr; bias = br; out = outr; C = DD;  cTile = (blockIdx.x - 16) * 64; }

    const int tid = threadIdx.x;
    const int tx = tid & 15;        // c quad
    const int ty = tid >> 4;        // n pair
    const int nTile = blockIdx.y * 32;

    __shared__ float As[64][33];    // [k][n]
    __shared__ float Bs[64][65];    // [k][c]

    float acc[2][4];
    #pragma unroll
    for (int i = 0; i < 2; i++)
        #pragma unroll
        for (int j = 0; j < 4; j++) acc[i][j] = 0.f;

    for (int k0 = 0; k0 < DD; k0 += 64) {
        // load As: 32 n-rows x 16 float4
        #pragma unroll
        for (int e = 0; e < 2; e++) {
            int linear = tid + e * 256;          // 0..511
            int nn = linear >> 4;                // 0..31
            int c4 = linear & 15;                // 0..15
            float4 v = *reinterpret_cast<const float4*>(
                g_summary + (nTile + nn) * DD + k0 + c4 * 4);
            As[c4 * 4 + 0][nn] = v.x;
            As[c4 * 4 + 1][nn] = v.y;
            As[c4 * 4 + 2][nn] = v.z;
            As[c4 * 4 + 3][nn] = v.w;
        }
        // load Bs: 64 c-rows x 16 float4
        #pragma unroll
        for (int e = 0; e < 4; e++) {
            int linear = tid + e * 256;          // 0..1023
            int rr = linear >> 4;                // 0..63
            int c4 = linear & 15;
            int cg = cTile + rr;
            float4 v = make_float4(0.f, 0.f, 0.f, 0.f);
            if (cg < C)
                v = *reinterpret_cast<const float4*>(W + (size_t)cg * DD + k0 + c4 * 4);
            Bs[c4 * 4 + 0][rr] = v.x;
            Bs[c4 * 4 + 1][rr] = v.y;
            Bs[c4 * 4 + 2][rr] = v.z;
            Bs[c4 * 4 + 3][rr] = v.w;
        }
        __syncthreads();

        #pragma unroll
        for (int kk = 0; kk < 64; kk++) {
            float a0 = As[kk][ty * 2 + 0];
            float a1 = As[kk][ty * 2 + 1];
            float b[4];
            #pragma unroll
            for (int j = 0; j < 4; j++) b[j] = Bs[kk][tx * 4 + j];
            #pragma unroll
            for (int j = 0; j < 4; j++) {
                acc[0][j] += a0 * b[j];
                acc[1][j] += a1 * b[j];
            }
        }
        __syncthreads();
    }

    #pragma unroll
    for (int i = 0; i < 2; i++) {
        int nn = nTile + ty * 2 + i;
        #pragma unroll
        for (int j = 0; j < 4; j++) {
            int cg = cTile + tx * 4 + j;
            if (cg < C) out[(size_t)nn * C + cg] = acc[i][j] + bias[cg];
        }
    }
}

extern "C" void kernel_launch(void* const* d_in, const int* in_sizes, int n_in,
                              void* d_out, int out_size) {
    const float* q     = (const float*)d_in[0];
    const float* Kmat  = (const float*)d_in[1];
    const float* Vmat  = (const float*)d_in[2];
    const float* W_cls = (const float*)d_in[3];
    const float* b_cls = (const float*)d_in[4];
    const float* W_rec = (const float*)d_in[5];
    const float* b_rec = (const float*)d_in[6];

    float* out = (float*)d_out;
    float* cls = out;
    float* rec = out + (size_t)NQ * CLS;
    float* wts = rec + (size_t)NQ * DD;

    attn_topk_kernel<<<NQ, 256>>>(q, Kmat, Vmat, wts);
    readout_gemm<<<dim3(18, NQ / 32), 256>>>(W_cls, b_cls, cls, W_rec, b_rec, rec);
}